// round 14
// baseline (speedup 1.0000x reference)
#include <cuda_runtime.h>
#include <cstdint>

#define NN    10000
#define NF    512
#define NH    32
#define NC    16
#define EMAX  360000
#define NT64  157                    // ceil(10000/64)
#define NTRI  (NT64 * (NT64 + 1) / 2)
#define NBG1  (NT64 * 4)             // gemm1 blocks (157 row-tiles x 4 k-chunks)
#define NBADD ((NN * NH / 4 + 255) / 256)

typedef unsigned long long ull;

// ---- scratch (static device globals; no allocation allowed) ----
__device__ float g_xw1p[4 * NN * NH];  // x @ W1 partials (4 K-chunks)
__device__ float g_xw1 [NN * NH];      // sum
__device__ float g_hw2 [NN * NC];      // h @ W2 (h kept in registers, fused)
__device__ float g_z   [NN * NC];      // A_hat @ hw2
__device__ int   g_counts[NN];         // zero-initialized; k_scan re-zeros after use
__device__ int   g_rowstart[NN + 1];
__device__ int   g_cursor[NN];
__device__ ull   g_cv[EMAX];           // packed (val<<32 | col)

// sigmoid(x) = 0.5*tanh(0.5x) + 0.5
__device__ __forceinline__ float sigmoidf(float v) {
    float t;
    asm("tanh.approx.f32 %0, %1;" : "=f"(t) : "f"(v * 0.5f));
    return fmaf(t, 0.5f, 0.5f);
}

// ---------------------------------------------------------------
// kernel 1: gemm1 (blocks [0, NBG1)) fused with dst-histogram (rest).
__global__ __launch_bounds__(256) void k_gemm1_hist(const float* __restrict__ x,
                                                    const float* __restrict__ W1,
                                                    const int* __restrict__ dst, int E) {
    __shared__ float xs[64][36];
    __shared__ float ws[32][36];
    const int tid = threadIdx.x;

    if (blockIdx.x >= NBG1) {           // ---- histogram blocks ----
        int base = (blockIdx.x - NBG1) * 1024 + tid;
#pragma unroll
        for (int j = 0; j < 4; j++) {
            int e = base + j * 256;
            if (e < E) atomicAdd(&g_counts[dst[e]], 1);
        }
        return;
    }

    // ---- gemm1 blocks ----
    const int tx  = tid & 7;
    const int ty  = tid >> 3;
    const int row0 = (blockIdx.x >> 2) * 64;
    const int kb   = blockIdx.x & 3;
    const int kbase = kb * 128;
    float* outbuf = g_xw1p + (size_t)kb * (NN * NH);

    float4 px[2], pw;
    {
        const int k0 = kbase;
#pragma unroll
        for (int j = 0; j < 2; j++) {
            int f = tid + 256 * j, r = f >> 3, kq = f & 7, gr = row0 + r;
            px[j] = make_float4(0.f, 0.f, 0.f, 0.f);
            if (gr < NN) px[j] = *(const float4*)&x[(size_t)gr * NF + k0 + kq * 4];
        }
        int r = tid >> 3, kq = tid & 7;
        pw = *(const float4*)&W1[(k0 + r) * NH + kq * 4];
    }

    float acc[2][4] = {};
    for (int kc = 0; kc < 4; kc++) {
#pragma unroll
        for (int j = 0; j < 2; j++) {
            int f = tid + 256 * j, r = f >> 3, kq = f & 7;
            *(float4*)&xs[r][kq * 4] = px[j];
        }
        {
            int r = tid >> 3, kq = tid & 7;
            *(float4*)&ws[r][kq * 4] = pw;
        }
        __syncthreads();
        if (kc < 3) {
            const int k0 = kbase + (kc + 1) * 32;
#pragma unroll
            for (int j = 0; j < 2; j++) {
                int f = tid + 256 * j, r = f >> 3, kq = f & 7, gr = row0 + r;
                px[j] = make_float4(0.f, 0.f, 0.f, 0.f);
                if (gr < NN) px[j] = *(const float4*)&x[(size_t)gr * NF + k0 + kq * 4];
            }
            int r = tid >> 3, kq = tid & 7;
            pw = *(const float4*)&W1[(k0 + r) * NH + kq * 4];
        }
#pragma unroll
        for (int kk = 0; kk < 32; kk++) {
            float a0 = xs[ty * 2 + 0][kk];
            float a1 = xs[ty * 2 + 1][kk];
            float4 b = *(float4*)&ws[kk][tx * 4];
            acc[0][0] += a0 * b.x; acc[0][1] += a0 * b.y;
            acc[0][2] += a0 * b.z; acc[0][3] += a0 * b.w;
            acc[1][0] += a1 * b.x; acc[1][1] += a1 * b.y;
            acc[1][2] += a1 * b.z; acc[1][3] += a1 * b.w;
        }
        __syncthreads();
    }
#pragma unroll
    for (int i = 0; i < 2; i++) {
        int gr = row0 + ty * 2 + i;
        if (gr < NN) {
            float4 o = make_float4(acc[i][0], acc[i][1], acc[i][2], acc[i][3]);
            *(float4*)&outbuf[gr * NH + tx * 4] = o;
        }
    }
}

// ---------------------------------------------------------------
__global__ void k_scan() {
    __shared__ int sums[1024];
    const int t = threadIdx.x;
    int loc[10];
    int s = 0;
#pragma unroll
    for (int j = 0; j < 10; j++) {
        int i = t * 10 + j;
        int c = (i < NN) ? g_counts[i] : 0;
        if (i < NN) g_counts[i] = 0;   // restore zero for next call
        loc[j] = s;
        s += c;
    }
    sums[t] = s;
    __syncthreads();
    for (int off = 1; off < 1024; off <<= 1) {
        int v = (t >= off) ? sums[t - off] : 0;
        __syncthreads();
        sums[t] += v;
        __syncthreads();
    }
    int base = (t > 0) ? sums[t - 1] : 0;
#pragma unroll
    for (int j = 0; j < 10; j++) {
        int i = t * 10 + j;
        if (i < NN) {
            int off = base + loc[j];
            g_rowstart[i] = off;
            g_cursor[i]   = off;
        }
    }
    if (t == 1023) g_rowstart[NN] = sums[1023];
}

// ---------------------------------------------------------------
// kernel 2: CSR scatter (blocks [0, nbS)) fused with xw1 partial-sum (rest).
__global__ __launch_bounds__(256) void k_scatter_add(const int* __restrict__ src,
                                                     const int* __restrict__ dst,
                                                     const float* __restrict__ w,
                                                     int E, int nbS) {
    const int tid = threadIdx.x;
    if (blockIdx.x < nbS) {             // ---- scatter blocks ----
        int base = blockIdx.x * 1024 + tid;
#pragma unroll
        for (int j = 0; j < 4; j++) {
            int e = base + j * 256;
            if (e < E) {
                int d = dst[e];
                int p = atomicAdd(&g_cursor[d], 1);
                ull cv = ((ull)__float_as_uint(w[e]) << 32) | (unsigned)src[e];
                g_cv[p] = cv;
            }
        }
    } else {                            // ---- add blocks ----
        int i = (blockIdx.x - nbS) * 256 + tid;
        if (i < NN * NH / 4) {
            float4 a = *(float4*)&g_xw1p[0 * NN * NH + i * 4];
            float4 b = *(float4*)&g_xw1p[1 * NN * NH + i * 4];
            float4 c = *(float4*)&g_xw1p[2 * NN * NH + i * 4];
            float4 d = *(float4*)&g_xw1p[3 * NN * NH + i * 4];
            float4 o = make_float4(a.x + b.x + c.x + d.x, a.y + b.y + c.y + d.y,
                                   a.z + b.z + c.z + d.z, a.w + b.w + c.w + d.w);
            *(float4*)&g_xw1[i * 4] = o;
        }
    }
}

// ---------------------------------------------------------------
// spmm1 + gemm2 FUSED: warp per row.
// h[row] = relu(A_hat @ xw1)[row] stays in registers (lane l = feature l);
// then hw2[row] = h[row] @ W2 via 16 shuffle-broadcast FMAs + xor-reduce.
// spmm uses 4 independent accumulators + 8-edge unroll to hide L2 latency.
__global__ __launch_bounds__(256) void k_spmm1_gemm2(const float* __restrict__ W2) {
    __shared__ float w2s[NH * NC];
    const int tid = threadIdx.x;
#pragma unroll
    for (int i = 0; i < 2; i++) w2s[tid + 256 * i] = W2[tid + 256 * i];
    __syncthreads();

    int warp = (blockIdx.x * blockDim.x + tid) >> 5;
    int l = tid & 31;
    if (warp >= NN) return;
    int start = g_rowstart[warp];
    int end   = g_rowstart[warp + 1];

    float a0 = 0.f, a1 = 0.f, a2 = 0.f, a3 = 0.f;
    int e = start;
    for (; e + 7 < end; e += 8) {
        ull cv0 = g_cv[e + 0], cv1 = g_cv[e + 1], cv2 = g_cv[e + 2], cv3 = g_cv[e + 3];
        ull cv4 = g_cv[e + 4], cv5 = g_cv[e + 5], cv6 = g_cv[e + 6], cv7 = g_cv[e + 7];
        float x0 = g_xw1[(int)(unsigned)cv0 * NH + l];
        float x1 = g_xw1[(int)(unsigned)cv1 * NH + l];
        float x2 = g_xw1[(int)(unsigned)cv2 * NH + l];
        float x3 = g_xw1[(int)(unsigned)cv3 * NH + l];
        float x4 = g_xw1[(int)(unsigned)cv4 * NH + l];
        float x5 = g_xw1[(int)(unsigned)cv5 * NH + l];
        float x6 = g_xw1[(int)(unsigned)cv6 * NH + l];
        float x7 = g_xw1[(int)(unsigned)cv7 * NH + l];
        a0 += __uint_as_float((unsigned)(cv0 >> 32)) * x0;
        a1 += __uint_as_float((unsigned)(cv1 >> 32)) * x1;
        a2 += __uint_as_float((unsigned)(cv2 >> 32)) * x2;
        a3 += __uint_as_float((unsigned)(cv3 >> 32)) * x3;
        a0 += __uint_as_float((unsigned)(cv4 >> 32)) * x4;
        a1 += __uint_as_float((unsigned)(cv5 >> 32)) * x5;
        a2 += __uint_as_float((unsigned)(cv6 >> 32)) * x6;
        a3 += __uint_as_float((unsigned)(cv7 >> 32)) * x7;
    }
    for (; e + 3 < end; e += 4) {
        ull cv0 = g_cv[e + 0], cv1 = g_cv[e + 1], cv2 = g_cv[e + 2], cv3 = g_cv[e + 3];
        a0 += __uint_as_float((unsigned)(cv0 >> 32)) * g_xw1[(int)(unsigned)cv0 * NH + l];
        a1 += __uint_as_float((unsigned)(cv1 >> 32)) * g_xw1[(int)(unsigned)cv1 * NH + l];
        a2 += __uint_as_float((unsigned)(cv2 >> 32)) * g_xw1[(int)(unsigned)cv2 * NH + l];
        a3 += __uint_as_float((unsigned)(cv3 >> 32)) * g_xw1[(int)(unsigned)cv3 * NH + l];
    }
    for (; e < end; e++) {
        ull cv = g_cv[e];
        a0 += __uint_as_float((unsigned)(cv >> 32)) * g_xw1[(int)(unsigned)cv * NH + l];
    }
    float h = fmaxf((a0 + a1) + (a2 + a3), 0.f);   // h[row][l], in-register

    // fused gemm2: lane l computes col (l&15) over rows [base, base+16)
    const int c    = l & 15;
    const int base = l & 16;
    float o = 0.f;
#pragma unroll
    for (int i = 0; i < 16; i++) {
        float hv = __shfl_sync(0xffffffffu, h, base + i);
        o += hv * w2s[(base + i) * NC + c];
    }
    o += __shfl_xor_sync(0xffffffffu, o, 16);
    if (l < 16) g_hw2[warp * NC + l] = o;
}

// spmm2: z = A_hat @ hw2. Warp per row; half-warps alternate edges; 2 accs.
__global__ void k_spmm2() {
    int warp = (blockIdx.x * blockDim.x + threadIdx.x) >> 5;
    int l = threadIdx.x & 31;
    if (warp >= NN) return;
    int f    = l & 15;
    int half = l >> 4;
    int start = g_rowstart[warp];
    int end   = g_rowstart[warp + 1];
    float a0 = 0.f, a1 = 0.f;
    int e = start + half;
    for (; e + 3 < end; e += 4) {
        ull cv0 = g_cv[e];
        ull cv1 = g_cv[e + 2];
        a0 += __uint_as_float((unsigned)(cv0 >> 32)) * g_hw2[(int)(unsigned)cv0 * NC + f];
        a1 += __uint_as_float((unsigned)(cv1 >> 32)) * g_hw2[(int)(unsigned)cv1 * NC + f];
    }
    for (; e < end; e += 2) {
        ull cv = g_cv[e];
        a0 += __uint_as_float((unsigned)(cv >> 32)) * g_hw2[(int)(unsigned)cv * NC + f];
    }
    float acc = a0 + a1;
    acc += __shfl_xor_sync(0xffffffffu, acc, 16);
    if (l < 16) g_z[warp * NC + l] = acc;
}

// ---------------------------------------------------------------
// decode: out = sigmoid(z @ z^T), SYMMETRIC. Upper-triangle 64x64 tiles
// (12403 blocks), 4x4 microtile (proven R5 geometry), tanh-based sigmoid.
__global__ __launch_bounds__(256) void k_decode(float* __restrict__ out) {
    __shared__ float zr[NC][68];
    __shared__ float zc[NC][68];
    const int t = blockIdx.x;
    int j = (int)((sqrtf(8.f * (float)t + 1.f) - 1.f) * 0.5f);
    while ((j + 1) * (j + 2) / 2 <= t) j++;
    while (j * (j + 1) / 2 > t) j--;
    const int i = t - j * (j + 1) / 2;
    const int r0 = i * 64;
    const int c0 = j * 64;
    const int tid = threadIdx.x;

    {
        int row = tid >> 2;   // 0..63
        int kq  = tid & 3;
        int gr = r0 + row;
        float4 v = (gr < NN) ? *(const float4*)&g_z[gr * NC + kq * 4]
                             : make_float4(0.f, 0.f, 0.f, 0.f);
        zr[kq * 4 + 0][row] = v.x; zr[kq * 4 + 1][row] = v.y;
        zr[kq * 4 + 2][row] = v.z; zr[kq * 4 + 3][row] = v.w;
        int gc = c0 + row;
        float4 w = (gc < NN) ? *(const float4*)&g_z[gc * NC + kq * 4]
                             : make_float4(0.f, 0.f, 0.f, 0.f);
        zc[kq * 4 + 0][row] = w.x; zc[kq * 4 + 1][row] = w.y;
        zc[kq * 4 + 2][row] = w.z; zc[kq * 4 + 3][row] = w.w;
    }
    __syncthreads();

    const int tx = tid & 15;
    const int ty = tid >> 4;

    float acc[4][4] = {};
#pragma unroll
    for (int k = 0; k < NC; k++) {
        float4 a = *(float4*)&zr[k][ty * 4];
        float4 b = *(float4*)&zc[k][tx * 4];
        acc[0][0] += a.x * b.x; acc[0][1] += a.x * b.y; acc[0][2] += a.x * b.z; acc[0][3] += a.x * b.w;
        acc[1][0] += a.y * b.x; acc[1][1] += a.y * b.y; acc[1][2] += a.y * b.z; acc[1][3] += a.y * b.w;
        acc[2][0] += a.z * b.x; acc[2][1] += a.z * b.y; acc[2][2] += a.z * b.z; acc[2][3] += a.z * b.w;
        acc[3][0] += a.w * b.x; acc[3][1] += a.w * b.y; acc[3][2] += a.w * b.z; acc[3][3] += a.w * b.w;
    }

    float s[4][4];
#pragma unroll
    for (int p = 0; p < 4; p++)
#pragma unroll
        for (int q = 0; q < 4; q++) s[p][q] = sigmoidf(acc[p][q]);

    const int gcb = c0 + tx * 4;
    if (gcb < NN) {
#pragma unroll
        for (int p = 0; p < 4; p++) {
            int gr = r0 + ty * 4 + p;
            if (gr < NN) {
                float4 o = make_float4(s[p][0], s[p][1], s[p][2], s[p][3]);
                *(float4*)&out[(size_t)gr * NN + gcb] = o;
            }
        }
    }

    if (i != j) {
        const int grb = r0 + ty * 4;
        if (grb < NN) {
#pragma unroll
            for (int q = 0; q < 4; q++) {
                int gc = c0 + tx * 4 + q;
                if (gc < NN) {
                    float4 o = make_float4(s[0][q], s[1][q], s[2][q], s[3][q]);
                    *(float4*)&out[(size_t)gc * NN + grb] = o;
                }
            }
        }
    }
}

// ---------------------------------------------------------------
extern "C" void kernel_launch(void* const* d_in, const int* in_sizes, int n_in,
                              void* d_out, int out_size) {
    const float* x   = (const float*)d_in[0];   // [10000, 512]
    const float* W1  = (const float*)d_in[1];   // [512, 32]
    const float* W2  = (const float*)d_in[2];   // [32, 16]
    const float* ew  = (const float*)d_in[3];   // [E]
    const int*   src = (const int*)d_in[4];     // [E]
    const int*   dst = (const int*)d_in[5];     // [E]
    float* out = (float*)d_out;
    const int E = in_sizes[3];

    const int nbS = (E + 1023) / 1024;

    k_gemm1_hist<<<NBG1 + nbS, 256>>>(x, W1, dst, E);           // gemm1 || hist
    k_scan<<<1, 1024>>>();
    k_scatter_add<<<nbS + NBADD, 256>>>(src, dst, ew, E, nbS);  // scatter || add
    k_spmm1_gemm2<<<(NN * 32 + 255) / 256, 256>>>(W2);          // spmm1 + gemm2 fused
    k_spmm2<<<(NN * 32 + 255) / 256, 256>>>();
    k_decode<<<NTRI, 256>>>(out);
}

// round 16
// speedup vs baseline: 1.4993x; 1.4993x over previous
#include <cuda_runtime.h>
#include <cstdint>

#define NN    10000
#define NF    512
#define NH    32
#define NC    16
#define EMAX  360000
#define NT64  157                    // ceil(10000/64)
#define NTRI  (NT64 * (NT64 + 1) / 2)
#define NBG1  (NT64 * 4)             // gemm1 blocks (157 row-tiles x 4 k-chunks)
#define NBADD ((NN * NH / 4 + 255) / 256)

typedef unsigned long long ull;

// ---- scratch (static device globals; no allocation allowed) ----
__device__ float g_xw1p[4 * NN * NH];  // x @ W1 partials (4 K-chunks)
__device__ float g_xw1 [NN * NH];      // sum
__device__ float g_h   [NN * NH];      // relu(A_hat @ xw1)
__device__ float g_hw2 [NN * NC];      // h @ W2
__device__ float g_z   [NN * NC];      // A_hat @ hw2
__device__ int   g_counts[NN];         // zero-initialized; k_scan re-zeros after use
__device__ int   g_rowstart[NN + 1];
__device__ int   g_cursor[NN];
__device__ ull   g_cv[EMAX];           // packed (val<<32 | col)

// sigmoid(x) = 0.5*tanh(0.5x) + 0.5
__device__ __forceinline__ float sigmoidf(float v) {
    float t;
    asm("tanh.approx.f32 %0, %1;" : "=f"(t) : "f"(v * 0.5f));
    return fmaf(t, 0.5f, 0.5f);
}

// ---------------------------------------------------------------
// kernel 1: gemm1 (blocks [0, NBG1)) fused with dst-histogram (rest).
__global__ __launch_bounds__(256) void k_gemm1_hist(const float* __restrict__ x,
                                                    const float* __restrict__ W1,
                                                    const int* __restrict__ dst, int E) {
    __shared__ float xs[64][36];
    __shared__ float ws[32][36];
    const int tid = threadIdx.x;

    if (blockIdx.x >= NBG1) {           // ---- histogram blocks ----
        int base = (blockIdx.x - NBG1) * 1024 + tid;
#pragma unroll
        for (int j = 0; j < 4; j++) {
            int e = base + j * 256;
            if (e < E) atomicAdd(&g_counts[dst[e]], 1);
        }
        return;
    }

    // ---- gemm1 blocks ----
    const int tx  = tid & 7;
    const int ty  = tid >> 3;
    const int row0 = (blockIdx.x >> 2) * 64;
    const int kb   = blockIdx.x & 3;
    const int kbase = kb * 128;
    float* outbuf = g_xw1p + (size_t)kb * (NN * NH);

    float4 px[2], pw;
    {
        const int k0 = kbase;
#pragma unroll
        for (int j = 0; j < 2; j++) {
            int f = tid + 256 * j, r = f >> 3, kq = f & 7, gr = row0 + r;
            px[j] = make_float4(0.f, 0.f, 0.f, 0.f);
            if (gr < NN) px[j] = *(const float4*)&x[(size_t)gr * NF + k0 + kq * 4];
        }
        int r = tid >> 3, kq = tid & 7;
        pw = *(const float4*)&W1[(k0 + r) * NH + kq * 4];
    }

    float acc[2][4] = {};
    for (int kc = 0; kc < 4; kc++) {
#pragma unroll
        for (int j = 0; j < 2; j++) {
            int f = tid + 256 * j, r = f >> 3, kq = f & 7;
            *(float4*)&xs[r][kq * 4] = px[j];
        }
        {
            int r = tid >> 3, kq = tid & 7;
            *(float4*)&ws[r][kq * 4] = pw;
        }
        __syncthreads();
        if (kc < 3) {
            const int k0 = kbase + (kc + 1) * 32;
#pragma unroll
            for (int j = 0; j < 2; j++) {
                int f = tid + 256 * j, r = f >> 3, kq = f & 7, gr = row0 + r;
                px[j] = make_float4(0.f, 0.f, 0.f, 0.f);
                if (gr < NN) px[j] = *(const float4*)&x[(size_t)gr * NF + k0 + kq * 4];
            }
            int r = tid >> 3, kq = tid & 7;
            pw = *(const float4*)&W1[(k0 + r) * NH + kq * 4];
        }
#pragma unroll
        for (int kk = 0; kk < 32; kk++) {
            float a0 = xs[ty * 2 + 0][kk];
            float a1 = xs[ty * 2 + 1][kk];
            float4 b = *(float4*)&ws[kk][tx * 4];
            acc[0][0] += a0 * b.x; acc[0][1] += a0 * b.y;
            acc[0][2] += a0 * b.z; acc[0][3] += a0 * b.w;
            acc[1][0] += a1 * b.x; acc[1][1] += a1 * b.y;
            acc[1][2] += a1 * b.z; acc[1][3] += a1 * b.w;
        }
        __syncthreads();
    }
#pragma unroll
    for (int i = 0; i < 2; i++) {
        int gr = row0 + ty * 2 + i;
        if (gr < NN) {
            float4 o = make_float4(acc[i][0], acc[i][1], acc[i][2], acc[i][3]);
            *(float4*)&outbuf[gr * NH + tx * 4] = o;
        }
    }
}

// ---------------------------------------------------------------
__global__ void k_scan() {
    __shared__ int sums[1024];
    const int t = threadIdx.x;
    int loc[10];
    int s = 0;
#pragma unroll
    for (int j = 0; j < 10; j++) {
        int i = t * 10 + j;
        int c = (i < NN) ? g_counts[i] : 0;
        if (i < NN) g_counts[i] = 0;   // restore zero for next call
        loc[j] = s;
        s += c;
    }
    sums[t] = s;
    __syncthreads();
    for (int off = 1; off < 1024; off <<= 1) {
        int v = (t >= off) ? sums[t - off] : 0;
        __syncthreads();
        sums[t] += v;
        __syncthreads();
    }
    int base = (t > 0) ? sums[t - 1] : 0;
#pragma unroll
    for (int j = 0; j < 10; j++) {
        int i = t * 10 + j;
        if (i < NN) {
            int off = base + loc[j];
            g_rowstart[i] = off;
            g_cursor[i]   = off;
        }
    }
    if (t == 1023) g_rowstart[NN] = sums[1023];
}

// ---------------------------------------------------------------
// kernel 2: CSR scatter (blocks [0, nbS)) fused with xw1 partial-sum (rest).
__global__ __launch_bounds__(256) void k_scatter_add(const int* __restrict__ src,
                                                     const int* __restrict__ dst,
                                                     const float* __restrict__ w,
                                                     int E, int nbS) {
    const int tid = threadIdx.x;
    if (blockIdx.x < nbS) {             // ---- scatter blocks ----
        int base = blockIdx.x * 1024 + tid;
#pragma unroll
        for (int j = 0; j < 4; j++) {
            int e = base + j * 256;
            if (e < E) {
                int d = dst[e];
                int p = atomicAdd(&g_cursor[d], 1);
                ull cv = ((ull)__float_as_uint(w[e]) << 32) | (unsigned)src[e];
                g_cv[p] = cv;
            }
        }
    } else {                            // ---- add blocks ----
        int i = (blockIdx.x - nbS) * 256 + tid;
        if (i < NN * NH / 4) {
            float4 a = *(float4*)&g_xw1p[0 * NN * NH + i * 4];
            float4 b = *(float4*)&g_xw1p[1 * NN * NH + i * 4];
            float4 c = *(float4*)&g_xw1p[2 * NN * NH + i * 4];
            float4 d = *(float4*)&g_xw1p[3 * NN * NH + i * 4];
            float4 o = make_float4(a.x + b.x + c.x + d.x, a.y + b.y + c.y + d.y,
                                   a.z + b.z + c.z + d.z, a.w + b.w + c.w + d.w);
            *(float4*)&g_xw1[i * 4] = o;
        }
    }
}

// ---------------------------------------------------------------
// spmm1: h = relu(A_hat @ xw1). Warp per row.
// ONLY change vs R13: 4 independent accumulators + 8-edge unroll to break
// the serial FFMA chain and double in-flight L2 loads.
__global__ void k_spmm1() {
    int warp = (blockIdx.x * blockDim.x + threadIdx.x) >> 5;
    int l = threadIdx.x & 31;
    if (warp >= NN) return;
    int start = g_rowstart[warp];
    int end   = g_rowstart[warp + 1];

    float a0 = 0.f, a1 = 0.f, a2 = 0.f, a3 = 0.f;
    int e = start;
    for (; e + 7 < end; e += 8) {
        ull cv0 = g_cv[e + 0], cv1 = g_cv[e + 1], cv2 = g_cv[e + 2], cv3 = g_cv[e + 3];
        ull cv4 = g_cv[e + 4], cv5 = g_cv[e + 5], cv6 = g_cv[e + 6], cv7 = g_cv[e + 7];
        float x0 = g_xw1[(int)(unsigned)cv0 * NH + l];
        float x1 = g_xw1[(int)(unsigned)cv1 * NH + l];
        float x2 = g_xw1[(int)(unsigned)cv2 * NH + l];
        float x3 = g_xw1[(int)(unsigned)cv3 * NH + l];
        float x4 = g_xw1[(int)(unsigned)cv4 * NH + l];
        float x5 = g_xw1[(int)(unsigned)cv5 * NH + l];
        float x6 = g_xw1[(int)(unsigned)cv6 * NH + l];
        float x7 = g_xw1[(int)(unsigned)cv7 * NH + l];
        a0 += __uint_as_float((unsigned)(cv0 >> 32)) * x0;
        a1 += __uint_as_float((unsigned)(cv1 >> 32)) * x1;
        a2 += __uint_as_float((unsigned)(cv2 >> 32)) * x2;
        a3 += __uint_as_float((unsigned)(cv3 >> 32)) * x3;
        a0 += __uint_as_float((unsigned)(cv4 >> 32)) * x4;
        a1 += __uint_as_float((unsigned)(cv5 >> 32)) * x5;
        a2 += __uint_as_float((unsigned)(cv6 >> 32)) * x6;
        a3 += __uint_as_float((unsigned)(cv7 >> 32)) * x7;
    }
    for (; e + 3 < end; e += 4) {
        ull cv0 = g_cv[e + 0], cv1 = g_cv[e + 1], cv2 = g_cv[e + 2], cv3 = g_cv[e + 3];
        a0 += __uint_as_float((unsigned)(cv0 >> 32)) * g_xw1[(int)(unsigned)cv0 * NH + l];
        a1 += __uint_as_float((unsigned)(cv1 >> 32)) * g_xw1[(int)(unsigned)cv1 * NH + l];
        a2 += __uint_as_float((unsigned)(cv2 >> 32)) * g_xw1[(int)(unsigned)cv2 * NH + l];
        a3 += __uint_as_float((unsigned)(cv3 >> 32)) * g_xw1[(int)(unsigned)cv3 * NH + l];
    }
    for (; e < end; e++) {
        ull cv = g_cv[e];
        a0 += __uint_as_float((unsigned)(cv >> 32)) * g_xw1[(int)(unsigned)cv * NH + l];
    }
    g_h[warp * NH + l] = fmaxf((a0 + a1) + (a2 + a3), 0.f);
}

// hw2 = h @ W2 (thread per row)  -- identical to R13
__global__ void k_gemm2(const float* __restrict__ W2) {
    __shared__ float w2s[NH * NC];
    const int tid = threadIdx.x;
    for (int i = tid; i < NH * NC; i += blockDim.x) w2s[i] = W2[i];
    __syncthreads();
    int row = blockIdx.x * blockDim.x + tid;
    if (row >= NN) return;
    float acc[NC] = {};
#pragma unroll
    for (int l = 0; l < NH; l++) {
        float hv = g_h[row * NH + l];
#pragma unroll
        for (int c = 0; c < NC; c++) acc[c] += hv * w2s[l * NC + c];
    }
#pragma unroll
    for (int q = 0; q < NC; q += 4) {
        float4 o = make_float4(acc[q], acc[q + 1], acc[q + 2], acc[q + 3]);
        *(float4*)&g_hw2[row * NC + q] = o;
    }
}

// spmm2: z = A_hat @ hw2 -- identical to R13
__global__ void k_spmm2() {
    int warp = (blockIdx.x * blockDim.x + threadIdx.x) >> 5;
    int l = threadIdx.x & 31;
    if (warp >= NN) return;
    int f    = l & 15;
    int half = l >> 4;
    int start = g_rowstart[warp];
    int end   = g_rowstart[warp + 1];
    float acc = 0.f;
    for (int e = start + half; e < end; e += 2) {
        ull cv = g_cv[e];
        int s = (int)(unsigned)cv;
        float w = __uint_as_float((unsigned)(cv >> 32));
        acc += w * g_hw2[s * NC + f];
    }
    acc += __shfl_xor_sync(0xffffffffu, acc, 16);
    if (l < 16) g_z[warp * NC + l] = acc;
}

// ---------------------------------------------------------------
// decode: identical to R13 (best-known). Upper-triangle 64x64 tiles.
__global__ __launch_bounds__(256) void k_decode(float* __restrict__ out) {
    __shared__ float zr[NC][68];
    __shared__ float zc[NC][68];
    const int t = blockIdx.x;
    int j = (int)((sqrtf(8.f * (float)t + 1.f) - 1.f) * 0.5f);
    while ((j + 1) * (j + 2) / 2 <= t) j++;
    while (j * (j + 1) / 2 > t) j--;
    const int i = t - j * (j + 1) / 2;
    const int r0 = i * 64;
    const int c0 = j * 64;
    const int tid = threadIdx.x;

    {
        int row = tid >> 2;   // 0..63
        int kq  = tid & 3;
        int gr = r0 + row;
        float4 v = (gr < NN) ? *(const float4*)&g_z[gr * NC + kq * 4]
                             : make_float4(0.f, 0.f, 0.f, 0.f);
        zr[kq * 4 + 0][row] = v.x; zr[kq * 4 + 1][row] = v.y;
        zr[kq * 4 + 2][row] = v.z; zr[kq * 4 + 3][row] = v.w;
        int gc = c0 + row;
        float4 w = (gc < NN) ? *(const float4*)&g_z[gc * NC + kq * 4]
                             : make_float4(0.f, 0.f, 0.f, 0.f);
        zc[kq * 4 + 0][row] = w.x; zc[kq * 4 + 1][row] = w.y;
        zc[kq * 4 + 2][row] = w.z; zc[kq * 4 + 3][row] = w.w;
    }
    __syncthreads();

    const int tx = tid & 15;
    const int ty = tid >> 4;

    float acc[4][4] = {};
#pragma unroll
    for (int k = 0; k < NC; k++) {
        float4 a = *(float4*)&zr[k][ty * 4];
        float4 b = *(float4*)&zc[k][tx * 4];
        acc[0][0] += a.x * b.x; acc[0][1] += a.x * b.y; acc[0][2] += a.x * b.z; acc[0][3] += a.x * b.w;
        acc[1][0] += a.y * b.x; acc[1][1] += a.y * b.y; acc[1][2] += a.y * b.z; acc[1][3] += a.y * b.w;
        acc[2][0] += a.z * b.x; acc[2][1] += a.z * b.y; acc[2][2] += a.z * b.z; acc[2][3] += a.z * b.w;
        acc[3][0] += a.w * b.x; acc[3][1] += a.w * b.y; acc[3][2] += a.w * b.z; acc[3][3] += a.w * b.w;
    }

    float s[4][4];
#pragma unroll
    for (int p = 0; p < 4; p++)
#pragma unroll
        for (int q = 0; q < 4; q++) s[p][q] = sigmoidf(acc[p][q]);

    const int gcb = c0 + tx * 4;
    if (gcb < NN) {
#pragma unroll
        for (int p = 0; p < 4; p++) {
            int gr = r0 + ty * 4 + p;
            if (gr < NN) {
                float4 o = make_float4(s[p][0], s[p][1], s[p][2], s[p][3]);
                *(float4*)&out[(size_t)gr * NN + gcb] = o;
            }
        }
    }

    if (i != j) {
        const int grb = r0 + ty * 4;
        if (grb < NN) {
#pragma unroll
            for (int q = 0; q < 4; q++) {
                int gc = c0 + tx * 4 + q;
                if (gc < NN) {
                    float4 o = make_float4(s[0][q], s[1][q], s[2][q], s[3][q]);
                    *(float4*)&out[(size_t)gc * NN + grb] = o;
                }
            }
        }
    }
}

// ---------------------------------------------------------------
extern "C" void kernel_launch(void* const* d_in, const int* in_sizes, int n_in,
                              void* d_out, int out_size) {
    const float* x   = (const float*)d_in[0];   // [10000, 512]
    const float* W1  = (const float*)d_in[1];   // [512, 32]
    const float* W2  = (const float*)d_in[2];   // [32, 16]
    const float* ew  = (const float*)d_in[3];   // [E]
    const int*   src = (const int*)d_in[4];     // [E]
    const int*   dst = (const int*)d_in[5];     // [E]
    float* out = (float*)d_out;
    const int E = in_sizes[3];

    const int nbS = (E + 1023) / 1024;

    k_gemm1_hist<<<NBG1 + nbS, 256>>>(x, W1, dst, E);           // gemm1 || hist
    k_scan<<<1, 1024>>>();
    k_scatter_add<<<nbS + NBADD, 256>>>(src, dst, ew, E, nbS);  // scatter || add
    k_spmm1<<<(NN * 32 + 255) / 256, 256>>>();
    k_gemm2<<<(NN + 255) / 256, 256>>>(W2);
    k_spmm2<<<(NN * 32 + 255) / 256, 256>>>();
    k_decode<<<NTRI, 256>>>(out);
}